// round 1
// baseline (speedup 1.0000x reference)
#include <cuda_runtime.h>
#include <math.h>

#define NN   50000
#define EE   1600000
#define ETOT 1650000
#define DIN_ 128

// ------------------------- device scratch (no allocs) -------------------------
__device__ float g_h[NN * 128];      // transformed features of current layer
__device__ float g_x[NN * 128];      // layer activations
__device__ float g_as[NN * 8];       // per-node src attention logits
__device__ float g_ad[NN * 8];       // per-node dst attention logits
__device__ int   g_counts[NN];
__device__ int   g_offs[NN + 1];
__device__ int   g_cursor[NN];
__device__ int   g_esrc[ETOT];
__device__ int   g_part[64];

// ------------------------- CSR build ------------------------------------------
__global__ void k_init(int* counts) {
    int i = blockIdx.x * 256 + threadIdx.x;
    if (i < NN) counts[i] = 1;  // self-loop
}

__global__ void k_hist(const int* __restrict__ A, int* counts) {
    int e = blockIdx.x * 256 + threadIdx.x;
    if (e < EE) atomicAdd(&counts[A[EE + e]], 1);
}

__global__ void k_scan1(const int* __restrict__ counts, int* offs, int* part) {
    __shared__ int sm[1024];
    int tid = threadIdx.x;
    int i = blockIdx.x * 1024 + tid;
    int v = (i < NN) ? counts[i] : 0;
    sm[tid] = v;
    __syncthreads();
    for (int off = 1; off < 1024; off <<= 1) {
        int t = (tid >= off) ? sm[tid - off] : 0;
        __syncthreads();
        sm[tid] += t;
        __syncthreads();
    }
    if (i < NN) offs[i + 1] = sm[tid];
    if (tid == 1023) part[blockIdx.x] = sm[1023];
}

__global__ void k_scan2(int* part, int nb) {
    if (threadIdx.x == 0) {
        int run = 0;
        for (int i = 0; i < nb; i++) { int t = part[i]; part[i] = run; run += t; }
    }
}

__global__ void k_scan3(int* offs, const int* __restrict__ part,
                        const int* __restrict__ counts, int* cursor) {
    int tid = threadIdx.x;
    int i = blockIdx.x * 1024 + tid;
    if (i < NN) {
        int val = offs[i + 1] + part[blockIdx.x];
        offs[i + 1] = val;
        cursor[i] = val - counts[i];
    }
    if (i == 0) offs[0] = 0;
}

__global__ void k_scatter(const int* __restrict__ A, int* cursor, int* esrc) {
    int idx = blockIdx.x * 256 + threadIdx.x;
    if (idx >= ETOT) return;
    int s, d;
    if (idx < EE) { s = A[idx]; d = A[EE + idx]; }
    else          { s = idx - EE; d = s; }
    int pos = atomicAdd(&cursor[d], 1);
    esrc[pos] = s;
}

// ------------------------- GEMM: h = x @ W  ------------------------------------
// BM=64 rows/block, full COLS width, thread tile 8x8, THREADS == COLS.
template <int COLS>
__global__ __launch_bounds__(COLS) void gemm_k(const float* __restrict__ X,
                                               const float* __restrict__ W,
                                               float* __restrict__ Hout) {
    constexpr int CT = COLS / 8;  // column threads
    constexpr int KT = 32;
    __shared__ float XsT[KT][68];     // transposed X tile, padded
    __shared__ float Ws[KT][COLS];

    const int t = threadIdx.x;
    const int tcol = t % CT;
    const int trow = t / CT;
    const int row0 = blockIdx.x * 64;

    float acc[8][8];
#pragma unroll
    for (int i = 0; i < 8; i++)
#pragma unroll
        for (int j = 0; j < 8; j++) acc[i][j] = 0.f;

    for (int kt = 0; kt < DIN_; kt += KT) {
        // load W tile: Ws[i][t] (coalesced)
#pragma unroll
        for (int i = 0; i < KT; i++) Ws[i][t] = W[(kt + i) * COLS + t];
        // load X tile transposed: 64 rows x 32 k
        {
            const int k = t & 31;
            const int rb = t >> 5;
            constexpr int STEP = COLS / 32;
#pragma unroll
            for (int r = rb; r < 64; r += STEP) {
                int gr = row0 + r;
                XsT[k][r] = (gr < NN) ? X[gr * DIN_ + kt + k] : 0.f;
            }
        }
        __syncthreads();
#pragma unroll 8
        for (int k = 0; k < KT; k++) {
            float4 a0 = *reinterpret_cast<const float4*>(&XsT[k][trow * 8]);
            float4 a1 = *reinterpret_cast<const float4*>(&XsT[k][trow * 8 + 4]);
            float aa[8] = {a0.x, a0.y, a0.z, a0.w, a1.x, a1.y, a1.z, a1.w};
            float bb[8];
#pragma unroll
            for (int j = 0; j < 8; j++) bb[j] = Ws[k][tcol + j * CT];
#pragma unroll
            for (int i = 0; i < 8; i++)
#pragma unroll
                for (int j = 0; j < 8; j++) acc[i][j] += aa[i] * bb[j];
        }
        __syncthreads();
    }
#pragma unroll
    for (int i = 0; i < 8; i++) {
        int r = row0 + trow * 8 + i;
        if (r < NN) {
#pragma unroll
            for (int j = 0; j < 8; j++) Hout[r * COLS + tcol + j * CT] = acc[i][j];
        }
    }
}

// ------------------------- attention logits per node ---------------------------
template <int H, int F>
__global__ __launch_bounds__(256) void attn_k(const float* __restrict__ Hb,
                                              const float* __restrict__ a_s,
                                              const float* __restrict__ a_d,
                                              float* __restrict__ ASRC,
                                              float* __restrict__ ADST) {
    int n = blockIdx.x * 8 + (threadIdx.x >> 5);
    if (n >= NN) return;
    int lane = threadIdx.x & 31;
    if constexpr (H * F == 128) {
        float4 hv = reinterpret_cast<const float4*>(Hb)[n * 32 + lane];
        int head = lane >> 2;
        int f0 = (lane & 3) * 4;
        const float* a = &a_s[head * F + f0];
        const float* d = &a_d[head * F + f0];
        float ps = hv.x * a[0] + hv.y * a[1] + hv.z * a[2] + hv.w * a[3];
        float pd = hv.x * d[0] + hv.y * d[1] + hv.z * d[2] + hv.w * d[3];
        ps += __shfl_xor_sync(~0u, ps, 1); ps += __shfl_xor_sync(~0u, ps, 2);
        pd += __shfl_xor_sync(~0u, pd, 1); pd += __shfl_xor_sync(~0u, pd, 2);
        if ((lane & 3) == 0) { ASRC[n * H + head] = ps; ADST[n * H + head] = pd; }
    } else {  // H*F == 64
        float2 hv = reinterpret_cast<const float2*>(Hb)[n * 32 + lane];
        int head = lane >> 3;
        int f0 = (lane & 7) * 2;
        float ps = hv.x * a_s[head * F + f0] + hv.y * a_s[head * F + f0 + 1];
        float pd = hv.x * a_d[head * F + f0] + hv.y * a_d[head * F + f0 + 1];
        ps += __shfl_xor_sync(~0u, ps, 1); ps += __shfl_xor_sync(~0u, ps, 2);
        ps += __shfl_xor_sync(~0u, ps, 4);
        pd += __shfl_xor_sync(~0u, pd, 1); pd += __shfl_xor_sync(~0u, pd, 2);
        pd += __shfl_xor_sync(~0u, pd, 4);
        if ((lane & 7) == 0) { ASRC[n * H + head] = ps; ADST[n * H + head] = pd; }
    }
}

// ------------------------- warp-per-node online-softmax aggregation ------------
template <int H, int F, bool RELU, bool MEAN>
__global__ __launch_bounds__(256) void agg_k(const float* __restrict__ Hb,
                                             const float* __restrict__ ASRC,
                                             const float* __restrict__ ADST,
                                             const int* __restrict__ esrc,
                                             const int* __restrict__ offs,
                                             const float* __restrict__ bias,
                                             float* __restrict__ out) {
    constexpr int HF = H * F;
    constexpr int VEC = HF / 32;
    int n = blockIdx.x * 8 + (threadIdx.x >> 5);
    if (n >= NN) return;
    int lane = threadIdx.x & 31;
    const int head = (lane * VEC) / F;

    const float adn = ADST[n * H + head];
    float m = -1e30f, s = 0.f;
    float acc[VEC];
#pragma unroll
    for (int v = 0; v < VEC; v++) acc[v] = 0.f;

    int e = offs[n];
    const int end = offs[n + 1];

    // software pipeline: 1-ahead prefetch of src / attn / feature row
    int src = esrc[e];
    float ea = ASRC[src * H + head];
    float hv[VEC];
    if constexpr (VEC == 4) {
        float4 t4 = reinterpret_cast<const float4*>(Hb)[src * 32 + lane];
        hv[0] = t4.x; hv[1] = t4.y; hv[2] = t4.z; hv[3] = t4.w;
    } else {
        float2 t2 = reinterpret_cast<const float2*>(Hb)[src * 32 + lane];
        hv[0] = t2.x; hv[1] = t2.y;
    }

    while (true) {
        int e2 = e + 1;
        bool more = e2 < end;
        float ea2 = 0.f;
        float hv2[VEC];
        if (more) {
            int src2 = esrc[e2];
            ea2 = ASRC[src2 * H + head];
            if constexpr (VEC == 4) {
                float4 t4 = reinterpret_cast<const float4*>(Hb)[src2 * 32 + lane];
                hv2[0] = t4.x; hv2[1] = t4.y; hv2[2] = t4.z; hv2[3] = t4.w;
            } else {
                float2 t2 = reinterpret_cast<const float2*>(Hb)[src2 * 32 + lane];
                hv2[0] = t2.x; hv2[1] = t2.y;
            }
        }
        float ev = ea + adn;
        ev = ev > 0.f ? ev : 0.2f * ev;   // leaky relu
        float mnew = fmaxf(m, ev);
        float scale = __expf(m - mnew);
        float p = __expf(ev - mnew);
        s = fmaf(s, scale, p);
#pragma unroll
        for (int v = 0; v < VEC; v++) acc[v] = fmaf(acc[v], scale, p * hv[v]);
        m = mnew;
        if (!more) break;
        e = e2;
        ea = ea2;
#pragma unroll
        for (int v = 0; v < VEC; v++) hv[v] = hv2[v];
    }

    const float inv = 1.f / (s + 1e-16f);
    if constexpr (!MEAN) {
        if constexpr (VEC == 4) {
            float4 o;
            o.x = acc[0] * inv + bias[lane * 4 + 0];
            o.y = acc[1] * inv + bias[lane * 4 + 1];
            o.z = acc[2] * inv + bias[lane * 4 + 2];
            o.w = acc[3] * inv + bias[lane * 4 + 3];
            if (RELU) {
                o.x = fmaxf(o.x, 0.f); o.y = fmaxf(o.y, 0.f);
                o.z = fmaxf(o.z, 0.f); o.w = fmaxf(o.w, 0.f);
            }
            reinterpret_cast<float4*>(out)[n * 32 + lane] = o;
        }
    } else {
        // VEC == 2: mean over heads, lanes l, l^8, l^16 same f-pair
        float ox = acc[0] * inv;
        float oy = acc[1] * inv;
        ox += __shfl_xor_sync(~0u, ox, 8);
        oy += __shfl_xor_sync(~0u, oy, 8);
        ox += __shfl_xor_sync(~0u, ox, 16);
        oy += __shfl_xor_sync(~0u, oy, 16);
        if (lane < 8) {
            out[n * 16 + 2 * lane]     = 0.25f * ox + bias[2 * lane];
            out[n * 16 + 2 * lane + 1] = 0.25f * oy + bias[2 * lane + 1];
        }
    }
}

// ------------------------- launcher -------------------------------------------
extern "C" void kernel_launch(void* const* d_in, const int* in_sizes, int n_in,
                              void* d_out, int out_size) {
    const float* X   = (const float*)d_in[0];
    const int*   A   = (const int*)d_in[1];
    const float* W1  = (const float*)d_in[2];
    const float* as1 = (const float*)d_in[3];
    const float* ad1 = (const float*)d_in[4];
    const float* b1  = (const float*)d_in[5];
    const float* W2  = (const float*)d_in[6];
    const float* as2 = (const float*)d_in[7];
    const float* ad2 = (const float*)d_in[8];
    const float* b2  = (const float*)d_in[9];
    const float* W3  = (const float*)d_in[10];
    const float* as3 = (const float*)d_in[11];
    const float* ad3 = (const float*)d_in[12];
    const float* b3  = (const float*)d_in[13];
    float* out = (float*)d_out;

    void* p;
    float *h, *x, *asb, *adb;
    int *counts, *offs, *cursor, *esrc, *part;
    cudaGetSymbolAddress(&p, g_h);      h = (float*)p;
    cudaGetSymbolAddress(&p, g_x);      x = (float*)p;
    cudaGetSymbolAddress(&p, g_as);     asb = (float*)p;
    cudaGetSymbolAddress(&p, g_ad);     adb = (float*)p;
    cudaGetSymbolAddress(&p, g_counts); counts = (int*)p;
    cudaGetSymbolAddress(&p, g_offs);   offs = (int*)p;
    cudaGetSymbolAddress(&p, g_cursor); cursor = (int*)p;
    cudaGetSymbolAddress(&p, g_esrc);   esrc = (int*)p;
    cudaGetSymbolAddress(&p, g_part);   part = (int*)p;

    const int NB = (NN + 1023) / 1024;  // 49

    // CSR by dst (counting sort), rebuilt every call (deterministic work)
    k_init<<<(NN + 255) / 256, 256>>>(counts);
    k_hist<<<(EE + 255) / 256, 256>>>(A, counts);
    k_scan1<<<NB, 1024>>>(counts, offs, part);
    k_scan2<<<1, 32>>>(part, NB);
    k_scan3<<<NB, 1024>>>(offs, part, counts, cursor);
    k_scatter<<<(ETOT + 255) / 256, 256>>>(A, cursor, esrc);

    const int GB = (NN + 63) / 64;   // gemm blocks
    const int AB = (NN + 7) / 8;     // warp-per-node blocks

    // Layer 1
    gemm_k<128><<<GB, 128>>>(X, W1, h);
    attn_k<8, 16><<<AB, 256>>>(h, as1, ad1, asb, adb);
    agg_k<8, 16, true, false><<<AB, 256>>>(h, asb, adb, esrc, offs, b1, x);
    // Layer 2
    gemm_k<128><<<GB, 128>>>(x, W2, h);
    attn_k<8, 16><<<AB, 256>>>(h, as2, ad2, asb, adb);
    agg_k<8, 16, true, false><<<AB, 256>>>(h, asb, adb, esrc, offs, b2, x);
    // Layer 3 (mean over heads)
    gemm_k<64><<<GB, 64>>>(x, W3, h);
    attn_k<4, 16><<<AB, 256>>>(h, as3, ad3, asb, adb);
    agg_k<4, 16, false, true><<<AB, 256>>>(h, asb, adb, esrc, offs, b3, out);
}